// round 4
// baseline (speedup 1.0000x reference)
#include <cuda_runtime.h>
#include <cuda_fp16.h>

#define Bq   512
#define Tt   365
#define Ff   16
#define Hh   256
#define G4   1024
#define NC   128     // CTAs
#define BS   4       // batch rows per CTA
#define NT   256     // threads: 4 gate cols x 4 batch each

typedef unsigned long long u64;

// ---------------------------------------------------------------------------
// fp16 weights (L2-resident), fp32 fused biases.
// g_w1: [272 rows][1024 cols]  (W_ih1 16 rows then W_hh1 256 rows)
// g_w2: [256 rows][256 groups][wa0..wa3, wb0..wb3]  (8 halves = 16B per thread)
// ---------------------------------------------------------------------------
__device__ __half g_w1[(Ff + Hh) * G4];
__device__ __half g_w2[Hh * 2 * G4];
__device__ float  g_b1[G4];
__device__ float  g_b2[G4];

// ---------------------------------------------------------------------------
__device__ __forceinline__ u64 fma2(u64 a, u64 b, u64 c) {
    u64 d; asm("fma.rn.f32x2 %0, %1, %2, %3;" : "=l"(d) : "l"(a), "l"(b), "l"(c)); return d;
}
// 2 fp16 -> packed f32x2 (2 SASS F2F with .H0/.H1 selectors)
__device__ __forceinline__ u64 cvt2(unsigned hw) {
    u64 r;
    asm("{\n\t"
        ".reg .b16 l, h;\n\t"
        ".reg .f32 f0, f1;\n\t"
        "mov.b32 {l, h}, %1;\n\t"
        "cvt.f32.f16 f0, l;\n\t"
        "cvt.f32.f16 f1, h;\n\t"
        "mov.b64 %0, {f0, f1};\n\t"
        "}" : "=l"(r) : "r"(hw));
    return r;
}
__device__ __forceinline__ float sigf(float x) { return 1.0f / (1.0f + __expf(-x)); }

// ---------------------------------------------------------------------------
// Prep: fp32 -> fp16, pack layouts, fuse biases.
// ---------------------------------------------------------------------------
__global__ void prep_kernel(const float* __restrict__ wih1, const float* __restrict__ whh1,
                            const float* __restrict__ bih1, const float* __restrict__ bhh1,
                            const float* __restrict__ wih2, const float* __restrict__ whh2,
                            const float* __restrict__ bih2, const float* __restrict__ bhh2) {
    int idx = blockIdx.x * blockDim.x + threadIdx.x;

    // g_w2: 256 * 2048 halves
    if (idx < Hh * 2 * G4) {
        int k = idx >> 11, r = idx & 2047;
        int grp = r >> 3, q = r & 7;
        float v;
        if (q < 4) { int col = grp * 4 + q;       v = wih2[col * Hh + k]; }
        else       { int col = grp * 4 + (q - 4); v = whh2[col * Hh + k]; }
        g_w2[idx] = __float2half_rn(v);
    }
    // g_w1: 272 * 1024 halves
    if (idx < (Ff + Hh) * G4) {
        int k = idx >> 10, col = idx & 1023;
        float v = (k < Ff) ? wih1[col * Ff + k] : whh1[col * Hh + (k - Ff)];
        g_w1[idx] = __float2half_rn(v);
    }
    if (idx < G4) {
        g_b1[idx] = bih1[idx] + bhh1[idx];
        g_b2[idx] = bih2[idx] + bhh2[idx];
    }
}

// ---------------------------------------------------------------------------
// Fused 2-layer LSTM. One CTA = 4 batch rows; state in SMEM; weights streamed.
// Gate phase: thread -> gate cols 4*tid..4*tid+3, all 4 batch rows (8 u64 acc).
// Update phase: thread -> unit u = tid, all 4 batch rows (c in registers).
// h stored DUPLICATED: hd[u][8] = {h0,h0,h1,h1,h2,h2,h3,h3}.
// ---------------------------------------------------------------------------
__global__ void __launch_bounds__(NT, 1)
lstm_kernel(const float* __restrict__ x,
            const float* __restrict__ wlin, const float* __restrict__ blin,
            float* __restrict__ out) {
    __shared__ float zs[BS * G4];      // zs[b][col]
    __shared__ float h1d[Hh * 8];
    __shared__ float h2d[Hh * 8];
    __shared__ float xs[Ff * 8];

    const int tid = threadIdx.x;
    const int b0  = blockIdx.x * BS;

    // zero state
    {
        float4 z4 = make_float4(0.f, 0.f, 0.f, 0.f);
        *(float4*)&h1d[tid * 8]     = z4;  *(float4*)&h1d[tid * 8 + 4] = z4;
        *(float4*)&h2d[tid * 8]     = z4;  *(float4*)&h2d[tid * 8 + 4] = z4;
    }
    float c1[4] = {0.f, 0.f, 0.f, 0.f};
    float c2[4] = {0.f, 0.f, 0.f, 0.f};

    const u64 b1lo = *(const u64*)&g_b1[4 * tid];
    const u64 b1hi = *(const u64*)&g_b1[4 * tid + 2];
    const u64 b2lo = *(const u64*)&g_b2[4 * tid];
    const u64 b2hi = *(const u64*)&g_b2[4 * tid + 2];

    const __half* w1p = &g_w1[4 * tid];            // 4 cols, rows 0..271
    const __half* w2p = &g_w2[8 * tid];            // [wa x4 | wb x4] per row

    __syncthreads();

    for (int t = 0; t < Tt; ++t) {
        // ---- stage x_t duplicated ----
        if (tid < Ff * BS) {
            int b = tid >> 4, f = tid & 15;
            float v = __ldg(&x[((size_t)(b0 + b) * Tt + t) * Ff + f]);
            *(float2*)&xs[f * 8 + 2 * b] = make_float2(v, v);
        }
        __syncthreads();

        // ================= LAYER 1 gates =================
        {
            u64 a00 = b1lo, a01 = b1lo, a02 = b1lo, a03 = b1lo;   // cols 4t,4t+1
            u64 a10 = b1hi, a11 = b1hi, a12 = b1hi, a13 = b1hi;   // cols 4t+2,4t+3
            #pragma unroll
            for (int k = 0; k < Ff; ++k) {
                uint2 wv = __ldg((const uint2*)(w1p + (size_t)k * G4));
                u64 w0 = cvt2(wv.x), w1 = cvt2(wv.y);
                ulonglong2 hA = *(const ulonglong2*)&xs[k * 8];
                ulonglong2 hB = *(const ulonglong2*)&xs[k * 8 + 4];
                a00 = fma2(w0, hA.x, a00); a01 = fma2(w0, hA.y, a01);
                a02 = fma2(w0, hB.x, a02); a03 = fma2(w0, hB.y, a03);
                a10 = fma2(w1, hA.x, a10); a11 = fma2(w1, hA.y, a11);
                a12 = fma2(w1, hB.x, a12); a13 = fma2(w1, hB.y, a13);
            }
            const __half* wh = w1p + Ff * G4;
            #pragma unroll 8
            for (int k = 0; k < Hh; ++k) {
                uint2 wv = __ldg((const uint2*)(wh + (size_t)k * G4));
                u64 w0 = cvt2(wv.x), w1 = cvt2(wv.y);
                ulonglong2 hA = *(const ulonglong2*)&h1d[k * 8];
                ulonglong2 hB = *(const ulonglong2*)&h1d[k * 8 + 4];
                a00 = fma2(w0, hA.x, a00); a01 = fma2(w0, hA.y, a01);
                a02 = fma2(w0, hB.x, a02); a03 = fma2(w0, hB.y, a03);
                a10 = fma2(w1, hA.x, a10); a11 = fma2(w1, hA.y, a11);
                a12 = fma2(w1, hB.x, a12); a13 = fma2(w1, hB.y, a13);
            }
            *(ulonglong2*)&zs[0 * G4 + 4 * tid] = make_ulonglong2(a00, a10);
            *(ulonglong2*)&zs[1 * G4 + 4 * tid] = make_ulonglong2(a01, a11);
            *(ulonglong2*)&zs[2 * G4 + 4 * tid] = make_ulonglong2(a02, a12);
            *(ulonglong2*)&zs[3 * G4 + 4 * tid] = make_ulonglong2(a03, a13);
        }
        __syncthreads();

        // ================= LAYER 1 update (unit u = tid) =================
        {
            const int u = tid;
            float h01[2], h23[2];
            #pragma unroll
            for (int b = 0; b < BS; ++b) {
                const float* zp = &zs[b * G4 + u];
                float zi = zp[0], zf = zp[Hh], zg = zp[2 * Hh], zo = zp[3 * Hh];
                c1[b] = sigf(zf) * c1[b] + sigf(zi) * tanhf(zg);
                float h = sigf(zo) * tanhf(c1[b]);
                if (b < 2) h01[b] = h; else h23[b - 2] = h;
            }
            *(float4*)&h1d[u * 8]     = make_float4(h01[0], h01[0], h01[1], h01[1]);
            *(float4*)&h1d[u * 8 + 4] = make_float4(h23[0], h23[0], h23[1], h23[1]);
        }
        __syncthreads();

        // ================= LAYER 2 gates =================
        {
            u64 a00 = b2lo, a01 = b2lo, a02 = b2lo, a03 = b2lo;
            u64 a10 = b2hi, a11 = b2hi, a12 = b2hi, a13 = b2hi;
            #pragma unroll 4
            for (int k = 0; k < Hh; ++k) {
                uint4 wv = __ldg((const uint4*)(w2p + (size_t)k * 2 * G4));
                u64 wa0 = cvt2(wv.x), wa1 = cvt2(wv.y);
                u64 wb0 = cvt2(wv.z), wb1 = cvt2(wv.w);
                ulonglong2 hA1 = *(const ulonglong2*)&h1d[k * 8];
                ulonglong2 hB1 = *(const ulonglong2*)&h1d[k * 8 + 4];
                ulonglong2 hA2 = *(const ulonglong2*)&h2d[k * 8];
                ulonglong2 hB2 = *(const ulonglong2*)&h2d[k * 8 + 4];
                a00 = fma2(wa0, hA1.x, a00); a01 = fma2(wa0, hA1.y, a01);
                a02 = fma2(wa0, hB1.x, a02); a03 = fma2(wa0, hB1.y, a03);
                a10 = fma2(wa1, hA1.x, a10); a11 = fma2(wa1, hA1.y, a11);
                a12 = fma2(wa1, hB1.x, a12); a13 = fma2(wa1, hB1.y, a13);
                a00 = fma2(wb0, hA2.x, a00); a01 = fma2(wb0, hA2.y, a01);
                a02 = fma2(wb0, hB2.x, a02); a03 = fma2(wb0, hB2.y, a03);
                a10 = fma2(wb1, hA2.x, a10); a11 = fma2(wb1, hA2.y, a11);
                a12 = fma2(wb1, hB2.x, a12); a13 = fma2(wb1, hB2.y, a13);
            }
            *(ulonglong2*)&zs[0 * G4 + 4 * tid] = make_ulonglong2(a00, a10);
            *(ulonglong2*)&zs[1 * G4 + 4 * tid] = make_ulonglong2(a01, a11);
            *(ulonglong2*)&zs[2 * G4 + 4 * tid] = make_ulonglong2(a02, a12);
            *(ulonglong2*)&zs[3 * G4 + 4 * tid] = make_ulonglong2(a03, a13);
        }
        __syncthreads();

        // ================= LAYER 2 update =================
        {
            const int u = tid;
            float h01[2], h23[2];
            #pragma unroll
            for (int b = 0; b < BS; ++b) {
                const float* zp = &zs[b * G4 + u];
                float zi = zp[0], zf = zp[Hh], zg = zp[2 * Hh], zo = zp[3 * Hh];
                c2[b] = sigf(zf) * c2[b] + sigf(zi) * tanhf(zg);
                float h = sigf(zo) * tanhf(c2[b]);
                if (b < 2) h01[b] = h; else h23[b - 2] = h;
            }
            *(float4*)&h2d[u * 8]     = make_float4(h01[0], h01[0], h01[1], h01[1]);
            *(float4*)&h2d[u * 8 + 4] = make_float4(h23[0], h23[0], h23[1], h23[1]);
        }
        __syncthreads();
    }

    // ================= linear head =================
    if (tid < 32 * BS) {
        int b = tid >> 5, lane = tid & 31;
        float s = 0.f;
        #pragma unroll
        for (int k = lane; k < Hh; k += 32) s += h2d[k * 8 + 2 * b] * __ldg(&wlin[k]);
        #pragma unroll
        for (int off = 16; off; off >>= 1) s += __shfl_xor_sync(0xffffffffu, s, off);
        if (lane == 0) out[b0 + b] = s + blin[0];
    }
}

// ---------------------------------------------------------------------------
extern "C" void kernel_launch(void* const* d_in, const int* in_sizes, int n_in,
                              void* d_out, int out_size) {
    const float* x    = (const float*)d_in[0];
    const float* wih1 = (const float*)d_in[1];
    const float* whh1 = (const float*)d_in[2];
    const float* bih1 = (const float*)d_in[3];
    const float* bhh1 = (const float*)d_in[4];
    const float* wih2 = (const float*)d_in[5];
    const float* whh2 = (const float*)d_in[6];
    const float* bih2 = (const float*)d_in[7];
    const float* bhh2 = (const float*)d_in[8];
    const float* wlin = (const float*)d_in[9];
    const float* blin = (const float*)d_in[10];
    float* out = (float*)d_out;

    prep_kernel<<<(Hh * 2 * G4 + 255) / 256, 256>>>(wih1, whh1, bih1, bhh1,
                                                    wih2, whh2, bih2, bhh2);
    lstm_kernel<<<NC, NT>>>(x, wlin, blin, out);
}

// round 5
// speedup vs baseline: 1.3428x; 1.3428x over previous
#include <cuda_runtime.h>
#include <cuda_fp16.h>

#define Bq   512
#define Tt   365
#define Ff   16
#define Hh   256
#define G4   1024
#define NC   128     // CTAs
#define BS   4       // batch rows per CTA
#define NT   512     // 2 k-halves x (4 gate cols x 4 batch)
#define KS1  120     // layer-1 h-row split (16 x-rows + 120 = 136 | 136)

typedef unsigned long long u64;

// ---------------------------------------------------------------------------
// fp16 weights (L2-resident), fp32 fused biases.
// g_w1: [272 rows][1024 cols]  (W_ih1 16 rows then W_hh1 256 rows)
// g_w2: [256 rows][256 groups][wa0..wa3, wb0..wb3]
// ---------------------------------------------------------------------------
__device__ __half g_w1[(Ff + Hh) * G4];
__device__ __half g_w2[Hh * 2 * G4];
__device__ float  g_b1[G4];
__device__ float  g_b2[G4];

__device__ __forceinline__ u64 fma2(u64 a, u64 b, u64 c) {
    u64 d; asm("fma.rn.f32x2 %0, %1, %2, %3;" : "=l"(d) : "l"(a), "l"(b), "l"(c)); return d;
}
__device__ __forceinline__ u64 cvt2(unsigned hw) {
    u64 r;
    asm("{\n\t"
        ".reg .b16 l, h;\n\t"
        ".reg .f32 f0, f1;\n\t"
        "mov.b32 {l, h}, %1;\n\t"
        "cvt.f32.f16 f0, l;\n\t"
        "cvt.f32.f16 f1, h;\n\t"
        "mov.b64 %0, {f0, f1};\n\t"
        "}" : "=l"(r) : "r"(hw));
    return r;
}
__device__ __forceinline__ float sigf(float x) { return 1.0f / (1.0f + __expf(-x)); }

// ---------------------------------------------------------------------------
__global__ void prep_kernel(const float* __restrict__ wih1, const float* __restrict__ whh1,
                            const float* __restrict__ bih1, const float* __restrict__ bhh1,
                            const float* __restrict__ wih2, const float* __restrict__ whh2,
                            const float* __restrict__ bih2, const float* __restrict__ bhh2) {
    int idx = blockIdx.x * blockDim.x + threadIdx.x;
    if (idx < Hh * 2 * G4) {
        int k = idx >> 11, r = idx & 2047;
        int grp = r >> 3, q = r & 7;
        float v;
        if (q < 4) { int col = grp * 4 + q;       v = wih2[col * Hh + k]; }
        else       { int col = grp * 4 + (q - 4); v = whh2[col * Hh + k]; }
        g_w2[idx] = __float2half_rn(v);
    }
    if (idx < (Ff + Hh) * G4) {
        int k = idx >> 10, col = idx & 1023;
        float v = (k < Ff) ? wih1[col * Ff + k] : whh1[col * Hh + (k - Ff)];
        g_w1[idx] = __float2half_rn(v);
    }
    if (idx < G4) {
        g_b1[idx] = bih1[idx] + bhh1[idx];
        g_b2[idx] = bih2[idx] + bhh2[idx];
    }
}

// ---------------------------------------------------------------------------
// Gate phase: thread (kh = tid>>8, ct = tid&255) -> gate cols 4ct..4ct+3,
//             all 4 batch rows, HALF of the k-range; partials in zsp[kh].
// Update phase: thread (u = tid&255, bh = tid>>8) -> unit u, batch 2bh..2bh+1.
// h duplicated: hd[u][8] = {h0,h0,h1,h1,h2,h2,h3,h3}.
// ---------------------------------------------------------------------------
__global__ void __launch_bounds__(NT, 1)
lstm_kernel(const float* __restrict__ x,
            const float* __restrict__ wlin, const float* __restrict__ blin,
            float* __restrict__ out) {
    __shared__ float zsp[2][BS * G4];
    __shared__ float h1d[Hh * 8];
    __shared__ float h2d[Hh * 8];
    __shared__ float xs[Ff * 8];

    const int tid = threadIdx.x;
    const int ct  = tid & 255;
    const int kh  = tid >> 8;
    const int b0  = blockIdx.x * BS;

    if (tid < Hh) {
        float4 z4 = make_float4(0.f, 0.f, 0.f, 0.f);
        *(float4*)&h1d[tid * 8]     = z4;  *(float4*)&h1d[tid * 8 + 4] = z4;
        *(float4*)&h2d[tid * 8]     = z4;  *(float4*)&h2d[tid * 8 + 4] = z4;
    }
    float c1[2] = {0.f, 0.f};
    float c2[2] = {0.f, 0.f};

    u64 b1lo = 0, b1hi = 0, b2lo = 0, b2hi = 0;
    if (kh == 0) {
        b1lo = *(const u64*)&g_b1[4 * ct];  b1hi = *(const u64*)&g_b1[4 * ct + 2];
        b2lo = *(const u64*)&g_b2[4 * ct];  b2hi = *(const u64*)&g_b2[4 * ct + 2];
    }

    const __half* w1p = &g_w1[4 * ct];
    const __half* w2p = &g_w2[8 * ct];

    __syncthreads();

    for (int t = 0; t < Tt; ++t) {
        // ---- stage x_t duplicated ----
        if (tid < Ff * BS) {
            int b = tid >> 4, f = tid & 15;
            float v = __ldg(&x[((size_t)(b0 + b) * Tt + t) * Ff + f]);
            *(float2*)&xs[f * 8 + 2 * b] = make_float2(v, v);
        }
        __syncthreads();

        // ================= LAYER 1 gates (k-split) =================
        {
            u64 a00 = b1lo, a01 = b1lo, a02 = b1lo, a03 = b1lo;
            u64 a10 = b1hi, a11 = b1hi, a12 = b1hi, a13 = b1hi;
            if (kh == 0) {
                #pragma unroll
                for (int k = 0; k < Ff; ++k) {
                    uint2 wv = __ldg((const uint2*)(w1p + (size_t)k * G4));
                    u64 w0 = cvt2(wv.x), w1 = cvt2(wv.y);
                    ulonglong2 hA = *(const ulonglong2*)&xs[k * 8];
                    ulonglong2 hB = *(const ulonglong2*)&xs[k * 8 + 4];
                    a00 = fma2(w0, hA.x, a00); a01 = fma2(w0, hA.y, a01);
                    a02 = fma2(w0, hB.x, a02); a03 = fma2(w0, hB.y, a03);
                    a10 = fma2(w1, hA.x, a10); a11 = fma2(w1, hA.y, a11);
                    a12 = fma2(w1, hB.x, a12); a13 = fma2(w1, hB.y, a13);
                }
                const __half* wh = w1p + Ff * G4;
                #pragma unroll 8
                for (int k = 0; k < KS1; ++k) {
                    uint2 wv = __ldg((const uint2*)(wh + (size_t)k * G4));
                    u64 w0 = cvt2(wv.x), w1 = cvt2(wv.y);
                    ulonglong2 hA = *(const ulonglong2*)&h1d[k * 8];
                    ulonglong2 hB = *(const ulonglong2*)&h1d[k * 8 + 4];
                    a00 = fma2(w0, hA.x, a00); a01 = fma2(w0, hA.y, a01);
                    a02 = fma2(w0, hB.x, a02); a03 = fma2(w0, hB.y, a03);
                    a10 = fma2(w1, hA.x, a10); a11 = fma2(w1, hA.y, a11);
                    a12 = fma2(w1, hB.x, a12); a13 = fma2(w1, hB.y, a13);
                }
            } else {
                const __half* wh = w1p + Ff * G4;
                #pragma unroll 8
                for (int k = KS1; k < Hh; ++k) {
                    uint2 wv = __ldg((const uint2*)(wh + (size_t)k * G4));
                    u64 w0 = cvt2(wv.x), w1 = cvt2(wv.y);
                    ulonglong2 hA = *(const ulonglong2*)&h1d[k * 8];
                    ulonglong2 hB = *(const ulonglong2*)&h1d[k * 8 + 4];
                    a00 = fma2(w0, hA.x, a00); a01 = fma2(w0, hA.y, a01);
                    a02 = fma2(w0, hB.x, a02); a03 = fma2(w0, hB.y, a03);
                    a10 = fma2(w1, hA.x, a10); a11 = fma2(w1, hA.y, a11);
                    a12 = fma2(w1, hB.x, a12); a13 = fma2(w1, hB.y, a13);
                }
            }
            float* zb = zsp[kh];
            *(ulonglong2*)&zb[0 * G4 + 4 * ct] = make_ulonglong2(a00, a10);
            *(ulonglong2*)&zb[1 * G4 + 4 * ct] = make_ulonglong2(a01, a11);
            *(ulonglong2*)&zb[2 * G4 + 4 * ct] = make_ulonglong2(a02, a12);
            *(ulonglong2*)&zb[3 * G4 + 4 * ct] = make_ulonglong2(a03, a13);
        }
        __syncthreads();

        // ================= LAYER 1 update =================
        {
            const int u = ct;
            float hv[2];
            #pragma unroll
            for (int j = 0; j < 2; ++j) {
                const int b = 2 * kh + j;
                const float* z0 = &zsp[0][b * G4 + u];
                const float* z1 = &zsp[1][b * G4 + u];
                float zi = z0[0]        + z1[0];
                float zf = z0[Hh]       + z1[Hh];
                float zg = z0[2 * Hh]   + z1[2 * Hh];
                float zo = z0[3 * Hh]   + z1[3 * Hh];
                c1[j] = sigf(zf) * c1[j] + sigf(zi) * tanhf(zg);
                hv[j] = sigf(zo) * tanhf(c1[j]);
            }
            *(float4*)&h1d[u * 8 + 4 * kh] = make_float4(hv[0], hv[0], hv[1], hv[1]);
        }
        __syncthreads();

        // ================= LAYER 2 gates (k-split) =================
        {
            u64 a00 = b2lo, a01 = b2lo, a02 = b2lo, a03 = b2lo;
            u64 a10 = b2hi, a11 = b2hi, a12 = b2hi, a13 = b2hi;
            const int k0 = kh * 128, k1 = k0 + 128;
            #pragma unroll 4
            for (int k = k0; k < k1; ++k) {
                uint4 wv = __ldg((const uint4*)(w2p + (size_t)k * 2 * G4));
                u64 wa0 = cvt2(wv.x), wa1 = cvt2(wv.y);
                u64 wb0 = cvt2(wv.z), wb1 = cvt2(wv.w);
                ulonglong2 hA1 = *(const ulonglong2*)&h1d[k * 8];
                ulonglong2 hB1 = *(const ulonglong2*)&h1d[k * 8 + 4];
                ulonglong2 hA2 = *(const ulonglong2*)&h2d[k * 8];
                ulonglong2 hB2 = *(const ulonglong2*)&h2d[k * 8 + 4];
                a00 = fma2(wa0, hA1.x, a00); a01 = fma2(wa0, hA1.y, a01);
                a02 = fma2(wa0, hB1.x, a02); a03 = fma2(wa0, hB1.y, a03);
                a10 = fma2(wa1, hA1.x, a10); a11 = fma2(wa1, hA1.y, a11);
                a12 = fma2(wa1, hB1.x, a12); a13 = fma2(wa1, hB1.y, a13);
                a00 = fma2(wb0, hA2.x, a00); a01 = fma2(wb0, hA2.y, a01);
                a02 = fma2(wb0, hB2.x, a02); a03 = fma2(wb0, hB2.y, a03);
                a10 = fma2(wb1, hA2.x, a10); a11 = fma2(wb1, hA2.y, a11);
                a12 = fma2(wb1, hB2.x, a12); a13 = fma2(wb1, hB2.y, a13);
            }
            float* zb = zsp[kh];
            *(ulonglong2*)&zb[0 * G4 + 4 * ct] = make_ulonglong2(a00, a10);
            *(ulonglong2*)&zb[1 * G4 + 4 * ct] = make_ulonglong2(a01, a11);
            *(ulonglong2*)&zb[2 * G4 + 4 * ct] = make_ulonglong2(a02, a12);
            *(ulonglong2*)&zb[3 * G4 + 4 * ct] = make_ulonglong2(a03, a13);
        }
        __syncthreads();

        // ================= LAYER 2 update =================
        {
            const int u = ct;
            float hv[2];
            #pragma unroll
            for (int j = 0; j < 2; ++j) {
                const int b = 2 * kh + j;
                const float* z0 = &zsp[0][b * G4 + u];
                const float* z1 = &zsp[1][b * G4 + u];
                float zi = z0[0]        + z1[0];
                float zf = z0[Hh]       + z1[Hh];
                float zg = z0[2 * Hh]   + z1[2 * Hh];
                float zo = z0[3 * Hh]   + z1[3 * Hh];
                c2[j] = sigf(zf) * c2[j] + sigf(zi) * tanhf(zg);
                hv[j] = sigf(zo) * tanhf(c2[j]);
            }
            *(float4*)&h2d[u * 8 + 4 * kh] = make_float4(hv[0], hv[0], hv[1], hv[1]);
        }
        __syncthreads();
    }

    // ================= linear head =================
    if (tid < 32 * BS) {
        int b = tid >> 5, lane = tid & 31;
        float s = 0.f;
        #pragma unroll
        for (int k = lane; k < Hh; k += 32) s += h2d[k * 8 + 2 * b] * __ldg(&wlin[k]);
        #pragma unroll
        for (int off = 16; off; off >>= 1) s += __shfl_xor_sync(0xffffffffu, s, off);
        if (lane == 0) out[b0 + b] = s + blin[0];
    }
}

// ---------------------------------------------------------------------------
extern "C" void kernel_launch(void* const* d_in, const int* in_sizes, int n_in,
                              void* d_out, int out_size) {
    const float* x    = (const float*)d_in[0];
    const float* wih1 = (const float*)d_in[1];
    const float* whh1 = (const float*)d_in[2];
    const float* bih1 = (const float*)d_in[3];
    const float* bhh1 = (const float*)d_in[4];
    const float* wih2 = (const float*)d_in[5];
    const float* whh2 = (const float*)d_in[6];
    const float* bih2 = (const float*)d_in[7];
    const float* bhh2 = (const float*)d_in[8];
    const float* wlin = (const float*)d_in[9];
    const float* blin = (const float*)d_in[10];
    float* out = (float*)d_out;

    prep_kernel<<<(Hh * 2 * G4 + 255) / 256, 256>>>(wih1, whh1, bih1, bhh1,
                                                    wih2, whh2, bih2, bhh2);
    lstm_kernel<<<NC, NT>>>(x, wlin, blin, out);
}